// round 8
// baseline (speedup 1.0000x reference)
#include <cuda_runtime.h>
#include <cuda_fp16.h>
#include <cstdint>

// out[B=256, N] = (inputs @ features^T) / 0.07
// R7: fp16 mma.sync GEMM — R3's exact math, split into 2 barrier domains.
// CTA: 256 thr / 8 warps (4m x 2n, warp tile 64x32), tile M=256 x N=64,
// K=256 in 8x KC=32, single-sync double-buffered pipeline.
// N-split (not M-split): F still read exactly once per row -> same DRAM
// traffic as R3, but 2 CTAs/SM (128 regs, 50KB smem) barrier independently,
// so one CTA's sync/load tail is covered by the other's warps.

#define KC 32
#define NITER 8
#define NT 64
#define ROWB 80u               // 64B k-row + 16B pad: conflict-free ldmatrix
#define ASTAGE 20480u          // 256 * 80
#define FSTAGE 5120u           // 64 * 80
#define OFF_F  (2u * ASTAGE)
#define SMEM_TOTAL (2 * 20480 + 2 * 5120)   // 51200
#define SCALE (1.0f / 0.07f)

__device__ __align__(16) __half g_A16[256 * 256];

// ---------------- helpers ----------------
__device__ __forceinline__ uint32_t smem_u32(const void* p) {
    uint32_t r;
    asm("{ .reg .u64 t; cvta.to.shared.u64 t, %1; cvt.u32.u64 %0, t; }" : "=r"(r) : "l"(p));
    return r;
}
__device__ __forceinline__ uint32_t pack_f16x2(float hi, float lo) {
    uint32_t r;
    asm("cvt.rn.f16x2.f32 %0, %1, %2;" : "=r"(r) : "f"(hi), "f"(lo));
    return r;
}
__device__ __forceinline__ void sts128(uint32_t a, uint32_t x, uint32_t y, uint32_t z, uint32_t w) {
    asm volatile("st.shared.v4.b32 [%0], {%1,%2,%3,%4};"
                 :: "r"(a), "r"(x), "r"(y), "r"(z), "r"(w) : "memory");
}
__device__ __forceinline__ void ldm4(uint32_t* r, uint32_t a) {
    asm volatile("ldmatrix.sync.aligned.m8n8.x4.shared.b16 {%0,%1,%2,%3}, [%4];"
                 : "=r"(r[0]), "=r"(r[1]), "=r"(r[2]), "=r"(r[3]) : "r"(a));
}
__device__ __forceinline__ void mma16816(float* d, const uint32_t* a, const uint32_t* b) {
    asm volatile("mma.sync.aligned.m16n8k16.row.col.f32.f16.f16.f32 "
                 "{%0,%1,%2,%3}, {%4,%5,%6,%7}, {%8,%9}, {%0,%1,%2,%3};"
                 : "+f"(d[0]), "+f"(d[1]), "+f"(d[2]), "+f"(d[3])
                 : "r"(a[0]), "r"(a[1]), "r"(a[2]), "r"(a[3]), "r"(b[0]), "r"(b[1]));
}
__device__ __forceinline__ void cp_async16(uint32_t dst, const void* src) {
    asm volatile("cp.async.cg.shared.global [%0], [%1], 16;" :: "r"(dst), "l"(src) : "memory");
}
#define CP_COMMIT asm volatile("cp.async.commit_group;" ::: "memory")
#define CP_WAIT0  asm volatile("cp.async.wait_group 0;" ::: "memory")

// ---------------- A convert kernel ----------------
__global__ void sct_cvtA(const float* __restrict__ A) {
    int i = blockIdx.x * 256 + threadIdx.x;   // 65536 elems
    g_A16[i] = __float2half_rn(A[i]);
}

// ---------------- main GEMM ----------------
__global__ __launch_bounds__(256, 2)
void sct_mma_kernel(const float* __restrict__ F, float* __restrict__ C, int N)
{
    extern __shared__ char smem[];
    const uint32_t sb = smem_u32(smem);          // A stages
    const uint32_t fb = sb + OFF_F;              // F stages
    const int tid  = threadIdx.x;
    const int lane = tid & 31;
    const int wid  = tid >> 5;
    const int n0   = blockIdx.x * NT;

    // A staging: 256 rows x 64B, thread t = row t, 4x 16B granules
    const uint32_t a_dst = (uint32_t)tid * ROWB;
    const __half* a_src = g_A16 + tid * 256;

    // F staging: row = tid>>2 (0..63), quarter = tid&3 -> 8 floats
    const int frow = tid >> 2;
    const int fq   = tid & 3;
    const int fn   = n0 + frow;
    const bool fvalid = (fn < N);
    const float* fsrc = F + (size_t)fn * 256 + fq * 8;
    const uint32_t f_sts = (uint32_t)frow * ROWB + (uint32_t)fq * 16u;

    // warp tiling: 4 m-warps x 2 n-warps, warp tile 64x32
    const int wm = wid & 3;
    const int wn = wid >> 2;
    const int mbase = wm * 64;
    const int nb    = wn * 32;

    const uint32_t afrag = (uint32_t)(mbase + (lane & 15)) * ROWB + (uint32_t)((lane >> 4) * 16);
    const uint32_t bfrag = (uint32_t)(nb + (lane & 7) + ((lane >> 4) << 3)) * ROWB
                         + (uint32_t)(((lane >> 3) & 1) << 4);

    float acc[4][4][4];
    #pragma unroll
    for (int i = 0; i < 4; i++)
        #pragma unroll
        for (int j = 0; j < 4; j++)
            #pragma unroll
            for (int q = 0; q < 4; q++) acc[i][j][q] = 0.0f;

    float4 pf0, pf1;

    auto cpA = [&](int s, int c) {
        const uint32_t dst = sb + s * ASTAGE + a_dst;
        const __half* src = a_src + c * KC;
        cp_async16(dst,      src);
        cp_async16(dst + 16, src + 8);
        cp_async16(dst + 32, src + 16);
        cp_async16(dst + 48, src + 24);
    };
    auto ldgF = [&](int c) {
        if (fvalid) {
            const float4* p = (const float4*)(fsrc + c * KC);
            pf0 = p[0]; pf1 = p[1];
        } else {
            pf0 = pf1 = make_float4(0.f, 0.f, 0.f, 0.f);
        }
    };
    auto stsF = [&](int s) {
        sts128(fb + s * FSTAGE + f_sts,
               pack_f16x2(pf0.y, pf0.x), pack_f16x2(pf0.w, pf0.z),
               pack_f16x2(pf1.y, pf1.x), pack_f16x2(pf1.w, pf1.z));
    };
    auto compute = [&](int s) {
        const uint32_t ast = sb + s * ASTAGE;
        const uint32_t fst = fb + s * FSTAGE;
        #pragma unroll
        for (int ks = 0; ks < 2; ks++) {
            const uint32_t ko = ks * 32;
            uint32_t b0[4], b1[4], a[4][4];
            ldm4(b0, fst + bfrag + ko);                  // n-tiles 0,1
            ldm4(b1, fst + bfrag + 16 * ROWB + ko);      // n-tiles 2,3
            #pragma unroll
            for (int i = 0; i < 4; i++)
                ldm4(a[i], ast + afrag + (uint32_t)i * (16 * ROWB) + ko);
            #pragma unroll
            for (int i = 0; i < 4; i++) {
                mma16816(acc[i][0], a[i], b0 + 0);
                mma16816(acc[i][1], a[i], b0 + 2);
                mma16816(acc[i][2], a[i], b1 + 0);
                mma16816(acc[i][3], a[i], b1 + 2);
            }
        }
    };

    // ---- prologue ----
    cpA(0, 0); CP_COMMIT;
    ldgF(0);
    stsF(0);
    CP_WAIT0;
    __syncthreads();

    // ---- mainloop (single sync per iter) ----
    for (int c = 0; c < NITER; c++) {
        const int cur = c & 1;
        const int nxt = cur ^ 1;
        if (c + 1 < NITER) {
            cpA(nxt, c + 1); CP_COMMIT;
            ldgF(c + 1);
        }
        compute(cur);
        if (c + 1 < NITER) {
            stsF(nxt);
            CP_WAIT0;
            __syncthreads();
        }
    }

    // ---- epilogue ----
    #pragma unroll
    for (int i = 0; i < 4; i++) {
        const int m = mbase + i * 16 + (lane >> 2);
        #pragma unroll
        for (int j = 0; j < 4; j++) {
            const int n = n0 + nb + j * 8 + (lane & 3) * 2;
            if (n < N) {   // N even, n even -> n+1 also valid
                float* p0 = C + (size_t)m * N + n;
                float* p1 = C + (size_t)(m + 8) * N + n;
                *(float2*)p0 = make_float2(acc[i][j][0] * SCALE, acc[i][j][1] * SCALE);
                *(float2*)p1 = make_float2(acc[i][j][2] * SCALE, acc[i][j][3] * SCALE);
            }
        }
    }
}

// ---------------- launch ----------------
extern "C" void kernel_launch(void* const* d_in, const int* in_sizes, int n_in,
                              void* d_out, int out_size)
{
    const float* inputs   = (const float*)d_in[0];  // [256, 256]
    const float* features = (const float*)d_in[2];  // [N, 256]
    const int D = 256;
    const int N = in_sizes[2] / D;

    sct_cvtA<<<256, 256>>>(inputs);

    cudaFuncSetAttribute(sct_mma_kernel, cudaFuncAttributeMaxDynamicSharedMemorySize, SMEM_TOTAL);
    int grid = (N + NT - 1) / NT;
    sct_mma_kernel<<<grid, 256, SMEM_TOTAL>>>(features, (float*)d_out, N);
}

// round 11
// speedup vs baseline: 1.0892x; 1.0892x over previous
#include <cuda_runtime.h>
#include <cuda_fp16.h>
#include <cstdint>

// out[B=256, N] = (inputs @ features^T) / 0.07
// R8: two-pass. Pass 1 converts F (and A) to fp16 in static device scratch.
// Pass 2 is a lean 4-stage cp.async multistage fp16 mma.sync GEMM:
// no convert / no STS / no LDG prefetch regs in the mainloop.
// CTA: 512 thr / 16 warps (4m x 4n, warp 64x32), tile M=256 x N=128,
// K=256 in 8x KC=32, one barrier per iter, cp.async.wait_group 2.

#define KC 32
#define NITER 8
#define NT 128
#define ROWB 80u               // 64B k-row + 16B pad: conflict-free ldmatrix
#define ASTAGE 20480u          // 256 * 80
#define FSTAGE 10240u          // 128 * 80
#define STAGE  (ASTAGE + FSTAGE)
#define NSTAGE 4
#define SMEM_TOTAL (NSTAGE * STAGE)     // 122880
#define SCALE (1.0f / 0.07f)
#define MAXN 131072

__device__ __align__(16) __half g_A16[256 * 256];
__device__ __align__(16) __half g_F16[(size_t)MAXN * 256];

// ---------------- helpers ----------------
__device__ __forceinline__ uint32_t smem_u32(const void* p) {
    uint32_t r;
    asm("{ .reg .u64 t; cvta.to.shared.u64 t, %1; cvt.u32.u64 %0, t; }" : "=r"(r) : "l"(p));
    return r;
}
__device__ __forceinline__ uint32_t pack_f16x2(float hi, float lo) {
    uint32_t r;
    asm("cvt.rn.f16x2.f32 %0, %1, %2;" : "=r"(r) : "f"(hi), "f"(lo));
    return r;
}
__device__ __forceinline__ void ldm4(uint32_t* r, uint32_t a) {
    asm volatile("ldmatrix.sync.aligned.m8n8.x4.shared.b16 {%0,%1,%2,%3}, [%4];"
                 : "=r"(r[0]), "=r"(r[1]), "=r"(r[2]), "=r"(r[3]) : "r"(a));
}
__device__ __forceinline__ void mma16816(float* d, const uint32_t* a, const uint32_t* b) {
    asm volatile("mma.sync.aligned.m16n8k16.row.col.f32.f16.f16.f32 "
                 "{%0,%1,%2,%3}, {%4,%5,%6,%7}, {%8,%9}, {%0,%1,%2,%3};"
                 : "+f"(d[0]), "+f"(d[1]), "+f"(d[2]), "+f"(d[3])
                 : "r"(a[0]), "r"(a[1]), "r"(a[2]), "r"(a[3]), "r"(b[0]), "r"(b[1]));
}
__device__ __forceinline__ void cp_async16(uint32_t dst, const void* src) {
    asm volatile("cp.async.cg.shared.global [%0], [%1], 16;" :: "r"(dst), "l"(src) : "memory");
}
__device__ __forceinline__ void cp_async16_z(uint32_t dst, const void* src, bool valid) {
    uint32_t sz = valid ? 16 : 0;
    asm volatile("cp.async.cg.shared.global [%0], [%1], 16, %2;"
                 :: "r"(dst), "l"(src), "r"(sz) : "memory");
}
#define CP_COMMIT asm volatile("cp.async.commit_group;" ::: "memory")
#define CP_WAIT(k) asm volatile("cp.async.wait_group %0;" :: "n"(k) : "memory")

// ---------------- convert kernels ----------------
__global__ void sct_cvtA(const float* __restrict__ A) {
    int i = blockIdx.x * 256 + threadIdx.x;   // 65536 elems
    g_A16[i] = __float2half_rn(A[i]);
}
// F: each thread converts 8 consecutive floats -> one uint4 of f16x2.
__global__ void sct_cvtF(const float* __restrict__ F, int total8) {
    int i = blockIdx.x * 256 + threadIdx.x;
    if (i >= total8) return;
    const float4* s = (const float4*)(F + (size_t)i * 8);
    float4 v0 = s[0], v1 = s[1];
    uint4 o;
    o.x = pack_f16x2(v0.y, v0.x);
    o.y = pack_f16x2(v0.w, v0.z);
    o.z = pack_f16x2(v1.y, v1.x);
    o.w = pack_f16x2(v1.w, v1.z);
    *(uint4*)(g_F16 + (size_t)i * 8) = o;
}

// ---------------- main GEMM ----------------
__global__ __launch_bounds__(512, 1)
void sct_mma_kernel(float* __restrict__ C, int N)
{
    extern __shared__ char smem[];
    const uint32_t sb = smem_u32(smem);
    const int tid  = threadIdx.x;
    const int lane = tid & 31;
    const int wid  = tid >> 5;
    const int n0   = blockIdx.x * NT;

    // A staging: row = tid>>1 (0..255), half = tid&1 (32B) -> 2 granules
    const int ar = tid >> 1;
    const int ah = tid & 1;
    const uint32_t a_dst = (uint32_t)ar * ROWB + (uint32_t)ah * 32u;
    const __half* a_src = g_A16 + ar * 256 + ah * 16;

    // F staging: row = tid>>2 (0..127), q = tid&3 (16B) -> 1 granule
    const int fr = tid >> 2;
    const int fq = tid & 3;
    const bool fvalid = (n0 + fr) < N;
    const uint32_t f_dst = ASTAGE + (uint32_t)fr * ROWB + (uint32_t)fq * 16u;
    const __half* f_src = g_F16 + (size_t)(n0 + fr) * 256 + fq * 8;

    // warp tiling: 4 m-warps x 4 n-warps, warp tile 64x32
    const int wm = wid & 3;
    const int wn = wid >> 2;
    const int mbase = wm * 64;
    const int nb    = wn * 32;

    const uint32_t afrag = (uint32_t)(mbase + (lane & 15)) * ROWB + (uint32_t)((lane >> 4) * 16);
    const uint32_t bfrag = ASTAGE
                         + (uint32_t)(nb + (lane & 7) + ((lane >> 4) << 3)) * ROWB
                         + (uint32_t)(((lane >> 3) & 1) << 4);

    float acc[4][4][4];
    #pragma unroll
    for (int i = 0; i < 4; i++)
        #pragma unroll
        for (int j = 0; j < 4; j++)
            #pragma unroll
            for (int q = 0; q < 4; q++) acc[i][j][q] = 0.0f;

    auto stage = [&](int c) {
        const uint32_t base = sb + (uint32_t)(c & 3) * STAGE;
        const __half* as = a_src + c * KC;
        cp_async16(base + a_dst,      as);
        cp_async16(base + a_dst + 16, as + 8);
        cp_async16_z(base + f_dst, f_src + c * KC, fvalid);
        CP_COMMIT;
    };
    auto compute = [&](int c) {
        const uint32_t base = sb + (uint32_t)(c & 3) * STAGE;
        #pragma unroll
        for (int ks = 0; ks < 2; ks++) {
            const uint32_t ko = ks * 32;
            uint32_t b0[4], b1[4], a[4][4];
            ldm4(b0, base + bfrag + ko);                 // n-tiles 0,1
            ldm4(b1, base + bfrag + 16 * ROWB + ko);     // n-tiles 2,3
            #pragma unroll
            for (int i = 0; i < 4; i++)
                ldm4(a[i], base + afrag + (uint32_t)i * (16 * ROWB) + ko);
            #pragma unroll
            for (int i = 0; i < 4; i++) {
                mma16816(acc[i][0], a[i], b0 + 0);
                mma16816(acc[i][1], a[i], b0 + 2);
                mma16816(acc[i][2], a[i], b1 + 0);
                mma16816(acc[i][3], a[i], b1 + 2);
            }
        }
    };

    // ---- prologue: stages 0,1 in flight ----
    stage(0);
    stage(1);

    // ---- mainloop: one barrier per iter, 2 groups always in flight ----
    #pragma unroll 1
    for (int c = 0; c < NITER; c++) {
        if (c + 2 < NITER) {
            stage(c + 2);
            CP_WAIT(2);
        } else if (c + 1 < NITER) {
            CP_WAIT(1);
        } else {
            CP_WAIT(0);
        }
        __syncthreads();
        compute(c);
    }

    // ---- epilogue ----
    #pragma unroll
    for (int i = 0; i < 4; i++) {
        const int m = mbase + i * 16 + (lane >> 2);
        #pragma unroll
        for (int j = 0; j < 4; j++) {
            const int n = n0 + nb + j * 8 + (lane & 3) * 2;
            if (n < N) {   // N even, n even -> n+1 also valid
                float* p0 = C + (size_t)m * N + n;
                float* p1 = C + (size_t)(m + 8) * N + n;
                *(float2*)p0 = make_float2(acc[i][j][0] * SCALE, acc[i][j][1] * SCALE);
                *(float2*)p1 = make_float2(acc[i][j][2] * SCALE, acc[i][j][3] * SCALE);
            }
        }
    }
}

// ---------------- launch ----------------
extern "C" void kernel_launch(void* const* d_in, const int* in_sizes, int n_in,
                              void* d_out, int out_size)
{
    const float* inputs   = (const float*)d_in[0];  // [256, 256]
    const float* features = (const float*)d_in[2];  // [N, 256]
    const int D = 256;
    const int N = in_sizes[2] / D;

    sct_cvtA<<<256, 256>>>(inputs);
    const int total8 = (N * D) / 8;
    sct_cvtF<<<(total8 + 255) / 256, 256>>>(features, total8);

    cudaFuncSetAttribute(sct_mma_kernel, cudaFuncAttributeMaxDynamicSharedMemorySize, SMEM_TOTAL);
    int grid = (N + NT - 1) / NT;
    sct_mma_kernel<<<grid, 512, SMEM_TOTAL>>>((float*)d_out, N);
}

// round 12
// speedup vs baseline: 1.4140x; 1.2982x over previous
#include <cuda_runtime.h>
#include <cuda_fp16.h>
#include <cstdint>

// out[B=256, N] = (inputs @ features^T) / 0.07
// R11: R3's winning shape (CTA M=256 x N=128, 512 thr, 16 warps 4mx4n,
// warp tile 64x32, KC=32, fused F fp32->fp16 convert) with a statically
// unrolled mainloop: A in a 4-stage cp.async ring issued 3 iters ahead
// (wait_group 2, off the barrier path), F in the proven LDG+cvt+STS double
// buffer prefetched 1 iter ahead. One __syncthreads per iteration.

#define KC 32
#define NITER 8
#define NT 128
#define ROWB 80u               // 64B k-row + 16B pad: conflict-free ldmatrix
#define ASTAGE 20480u          // 256 * 80
#define FSTAGE 10240u          // 128 * 80
#define OFF_F  (4u * ASTAGE)
#define SMEM_TOTAL (4 * 20480 + 2 * 10240)   // 102400
#define SCALE (1.0f / 0.07f)

__device__ __align__(16) __half g_A16[256 * 256];

// ---------------- helpers ----------------
__device__ __forceinline__ uint32_t smem_u32(const void* p) {
    uint32_t r;
    asm("{ .reg .u64 t; cvta.to.shared.u64 t, %1; cvt.u32.u64 %0, t; }" : "=r"(r) : "l"(p));
    return r;
}
__device__ __forceinline__ uint32_t pack_f16x2(float hi, float lo) {
    uint32_t r;
    asm("cvt.rn.f16x2.f32 %0, %1, %2;" : "=r"(r) : "f"(hi), "f"(lo));
    return r;
}
__device__ __forceinline__ void sts128(uint32_t a, uint32_t x, uint32_t y, uint32_t z, uint32_t w) {
    asm volatile("st.shared.v4.b32 [%0], {%1,%2,%3,%4};"
                 :: "r"(a), "r"(x), "r"(y), "r"(z), "r"(w) : "memory");
}
__device__ __forceinline__ void ldm4(uint32_t* r, uint32_t a) {
    asm volatile("ldmatrix.sync.aligned.m8n8.x4.shared.b16 {%0,%1,%2,%3}, [%4];"
                 : "=r"(r[0]), "=r"(r[1]), "=r"(r[2]), "=r"(r[3]) : "r"(a));
}
__device__ __forceinline__ void mma16816(float* d, const uint32_t* a, const uint32_t* b) {
    asm volatile("mma.sync.aligned.m16n8k16.row.col.f32.f16.f16.f32 "
                 "{%0,%1,%2,%3}, {%4,%5,%6,%7}, {%8,%9}, {%0,%1,%2,%3};"
                 : "+f"(d[0]), "+f"(d[1]), "+f"(d[2]), "+f"(d[3])
                 : "r"(a[0]), "r"(a[1]), "r"(a[2]), "r"(a[3]), "r"(b[0]), "r"(b[1]));
}
__device__ __forceinline__ void cp_async16(uint32_t dst, const void* src) {
    asm volatile("cp.async.cg.shared.global [%0], [%1], 16;" :: "r"(dst), "l"(src) : "memory");
}
#define CP_COMMIT asm volatile("cp.async.commit_group;" ::: "memory")
#define CP_WAIT(k) asm volatile("cp.async.wait_group %0;" :: "n"(k) : "memory")

// ---------------- A convert kernel ----------------
__global__ void sct_cvtA(const float* __restrict__ A) {
    int i = blockIdx.x * 256 + threadIdx.x;   // 65536 elems
    g_A16[i] = __float2half_rn(A[i]);
}

// ---------------- main GEMM ----------------
__global__ __launch_bounds__(512, 1)
void sct_mma_kernel(const float* __restrict__ F, float* __restrict__ C, int N)
{
    extern __shared__ char smem[];
    const uint32_t sb = smem_u32(smem);          // A ring (4 stages)
    const uint32_t fb = sb + OFF_F;              // F stages (2)
    const int tid  = threadIdx.x;
    const int lane = tid & 31;
    const int wid  = tid >> 5;
    const int n0   = blockIdx.x * NT;

    // A staging: row = tid>>1 (0..255), half = tid&1 (32B) -> 2 granules
    const int ar = tid >> 1;
    const int ah = tid & 1;
    const uint32_t a_dst = (uint32_t)ar * ROWB + (uint32_t)ah * 32u;
    const __half* a_src = g_A16 + ar * 256 + ah * 16;

    // F staging: row = tid>>2 (0..127), q = tid&3 -> 8 floats (32B)
    const int frow = tid >> 2;
    const int fq   = tid & 3;
    int fn = n0 + frow;
    if (fn > N - 1) fn = N - 1;                  // clamp: no branch, stores guarded
    const float* fsrc = F + (size_t)fn * 256 + fq * 8;
    const uint32_t f_sts = (uint32_t)frow * ROWB + (uint32_t)fq * 16u;

    // warp tiling: 4 m-warps x 4 n-warps, warp tile 64x32
    const int wm = wid & 3;
    const int wn = wid >> 2;
    const int mbase = wm * 64;
    const int nb    = wn * 32;

    const uint32_t afrag = (uint32_t)(mbase + (lane & 15)) * ROWB + (uint32_t)((lane >> 4) * 16);
    const uint32_t bfrag = (uint32_t)(nb + (lane & 7) + ((lane >> 4) << 3)) * ROWB
                         + (uint32_t)(((lane >> 3) & 1) << 4);

    float acc[4][4][4];
    #pragma unroll
    for (int i = 0; i < 4; i++)
        #pragma unroll
        for (int j = 0; j < 4; j++)
            #pragma unroll
            for (int q = 0; q < 4; q++) acc[i][j][q] = 0.0f;

    float4 pf0, pf1;

    auto cpA = [&](int c) {
        const uint32_t dst = sb + (uint32_t)(c & 3) * ASTAGE + a_dst;
        const __half* src = a_src + c * KC;
        cp_async16(dst,      src);
        cp_async16(dst + 16, src + 8);
        CP_COMMIT;
    };
    auto ldgF = [&](int c) {
        const float4* p = (const float4*)(fsrc + c * KC);
        pf0 = p[0]; pf1 = p[1];
    };
    auto stsF = [&](int c) {
        sts128(fb + (uint32_t)(c & 1) * FSTAGE + f_sts,
               pack_f16x2(pf0.y, pf0.x), pack_f16x2(pf0.w, pf0.z),
               pack_f16x2(pf1.y, pf1.x), pack_f16x2(pf1.w, pf1.z));
    };
    auto compute = [&](int c) {
        const uint32_t ast = sb + (uint32_t)(c & 3) * ASTAGE;
        const uint32_t fst = fb + (uint32_t)(c & 1) * FSTAGE;
        #pragma unroll
        for (int ks = 0; ks < 2; ks++) {
            const uint32_t ko = ks * 32;
            uint32_t b0[4], b1[4], a[4][4];
            ldm4(b0, fst + bfrag + ko);                  // n-tiles 0,1
            ldm4(b1, fst + bfrag + 16 * ROWB + ko);      // n-tiles 2,3
            #pragma unroll
            for (int i = 0; i < 4; i++)
                ldm4(a[i], ast + afrag + (uint32_t)i * (16 * ROWB) + ko);
            #pragma unroll
            for (int i = 0; i < 4; i++) {
                mma16816(acc[i][0], a[i], b0 + 0);
                mma16816(acc[i][1], a[i], b0 + 2);
                mma16816(acc[i][2], a[i], b1 + 0);
                mma16816(acc[i][3], a[i], b1 + 2);
            }
        }
    };

    // ---- prologue: A stages 0..2 in flight, F stage 0 staged ----
    cpA(0);
    cpA(1);
    cpA(2);
    ldgF(0);
    stsF(0);
    CP_WAIT(2);          // A0 complete
    __syncthreads();

    // ---- mainloop: fully unrolled, static stage indices ----
    #pragma unroll
    for (int c = 0; c < NITER; c++) {
        if (c + 1 < NITER) ldgF(c + 1);
        compute(c);
        if (c + 1 < NITER) {
            stsF(c + 1);
            if (c + 3 < NITER) { cpA(c + 3); CP_WAIT(2); }
            else if (c + 2 < NITER) CP_WAIT(1);
            else CP_WAIT(0);
            __syncthreads();
        }
    }

    // ---- epilogue ----
    #pragma unroll
    for (int i = 0; i < 4; i++) {
        const int m = mbase + i * 16 + (lane >> 2);
        #pragma unroll
        for (int j = 0; j < 4; j++) {
            const int n = n0 + nb + j * 8 + (lane & 3) * 2;
            if (n < N) {   // N even, n even -> n+1 also valid
                float* p0 = C + (size_t)m * N + n;
                float* p1 = C + (size_t)(m + 8) * N + n;
                *(float2*)p0 = make_float2(acc[i][j][0] * SCALE, acc[i][j][1] * SCALE);
                *(float2*)p1 = make_float2(acc[i][j][2] * SCALE, acc[i][j][3] * SCALE);
            }
        }
    }
}

// ---------------- launch ----------------
extern "C" void kernel_launch(void* const* d_in, const int* in_sizes, int n_in,
                              void* d_out, int out_size)
{
    const float* inputs   = (const float*)d_in[0];  // [256, 256]
    const float* features = (const float*)d_in[2];  // [N, 256]
    const int D = 256;
    const int N = in_sizes[2] / D;

    sct_cvtA<<<256, 256>>>(inputs);

    cudaFuncSetAttribute(sct_mma_kernel, cudaFuncAttributeMaxDynamicSharedMemorySize, SMEM_TOTAL);
    int grid = (N + NT - 1) / NT;
    sct_mma_kernel<<<grid, 512, SMEM_TOTAL>>>(features, (float*)d_out, N);
}

// round 13
// speedup vs baseline: 1.6332x; 1.1550x over previous
#include <cuda_runtime.h>
#include <cuda_fp16.h>
#include <cstdint>

// out[B=256, N] = (inputs @ features^T) / 0.07
// R12: persistent-CTA fp16 mma.sync GEMM with A fully resident in smem.
// Inner loop identical to the proven R3/R11 shape: 512 thr / 16 warps
// (4m x 4n, warp tile 64x32), tile M=256 x N=128, KC=32, F fp32->fp16
// fused convert in a single-sync double buffer. A (all 8 k-chunks, 160KB,
// 80B-stride conflict-free layout) is cp.async'd ONCE per CTA; the inner
// loop has zero A staging. Grid = #SMs (1 CTA/SM), tiles strided, and the
// next tile's F LDG issues before the epilogue so C stores hide it.

#define KC 32
#define NCH 8
#define NT 128
#define ROWB 80u                 // 64B k-row + 16B pad
#define ACHUNK 20480u            // 256 rows * 80B per k-chunk
#define ARES   (8u * ACHUNK)     // 163840
#define OFF_F  ARES
#define FSTAGE 10240u            // 128 * 80
#define SMEM_TOTAL (163840 + 2 * 10240)   // 184320
#define SCALE (1.0f / 0.07f)

__device__ __align__(16) __half g_A16[256 * 256];

// ---------------- helpers ----------------
__device__ __forceinline__ uint32_t smem_u32(const void* p) {
    uint32_t r;
    asm("{ .reg .u64 t; cvta.to.shared.u64 t, %1; cvt.u32.u64 %0, t; }" : "=r"(r) : "l"(p));
    return r;
}
__device__ __forceinline__ uint32_t pack_f16x2(float hi, float lo) {
    uint32_t r;
    asm("cvt.rn.f16x2.f32 %0, %1, %2;" : "=r"(r) : "f"(hi), "f"(lo));
    return r;
}
__device__ __forceinline__ void sts128(uint32_t a, uint32_t x, uint32_t y, uint32_t z, uint32_t w) {
    asm volatile("st.shared.v4.b32 [%0], {%1,%2,%3,%4};"
                 :: "r"(a), "r"(x), "r"(y), "r"(z), "r"(w) : "memory");
}
__device__ __forceinline__ void ldm4(uint32_t* r, uint32_t a) {
    asm volatile("ldmatrix.sync.aligned.m8n8.x4.shared.b16 {%0,%1,%2,%3}, [%4];"
                 : "=r"(r[0]), "=r"(r[1]), "=r"(r[2]), "=r"(r[3]) : "r"(a));
}
__device__ __forceinline__ void mma16816(float* d, const uint32_t* a, const uint32_t* b) {
    asm volatile("mma.sync.aligned.m16n8k16.row.col.f32.f16.f16.f32 "
                 "{%0,%1,%2,%3}, {%4,%5,%6,%7}, {%8,%9}, {%0,%1,%2,%3};"
                 : "+f"(d[0]), "+f"(d[1]), "+f"(d[2]), "+f"(d[3])
                 : "r"(a[0]), "r"(a[1]), "r"(a[2]), "r"(a[3]), "r"(b[0]), "r"(b[1]));
}
__device__ __forceinline__ void cp_async16(uint32_t dst, const void* src) {
    asm volatile("cp.async.cg.shared.global [%0], [%1], 16;" :: "r"(dst), "l"(src) : "memory");
}
#define CP_COMMIT asm volatile("cp.async.commit_group;" ::: "memory")
#define CP_WAIT0  asm volatile("cp.async.wait_group 0;" ::: "memory")

// ---------------- A convert kernel ----------------
__global__ void sct_cvtA(const float* __restrict__ A) {
    int i = blockIdx.x * 256 + threadIdx.x;   // 65536 elems
    g_A16[i] = __float2half_rn(A[i]);
}

// ---------------- main GEMM (persistent) ----------------
__global__ __launch_bounds__(512, 1)
void sct_mma_kernel(const float* __restrict__ F, float* __restrict__ C,
                    int N, int ntiles)
{
    extern __shared__ char smem[];
    const uint32_t sb = smem_u32(smem);          // A resident: 8 chunks
    const uint32_t fb = sb + OFF_F;              // F stages (2)
    const int tid  = threadIdx.x;
    const int lane = tid & 31;
    const int wid  = tid >> 5;

    // ---- A residency load: once per CTA ----
    {
        const int ar = tid >> 1;                 // row 0..255
        const int ah = tid & 1;                  // 32B half
        const uint32_t dst0 = (uint32_t)ar * ROWB + (uint32_t)ah * 32u;
        const __half* src0 = g_A16 + ar * 256 + ah * 16;
        #pragma unroll
        for (int c = 0; c < NCH; c++) {
            const uint32_t dst = sb + (uint32_t)c * ACHUNK + dst0;
            const __half* src = src0 + c * KC;
            cp_async16(dst,      src);
            cp_async16(dst + 16, src + 8);
        }
        CP_COMMIT;
    }

    // F staging: row = tid>>2 (0..127), q = tid&3 -> 8 floats (32B)
    const int frow = tid >> 2;
    const int fq   = tid & 3;
    const uint32_t f_sts = (uint32_t)frow * ROWB + (uint32_t)fq * 16u;

    // warp tiling: 4 m-warps x 4 n-warps, warp tile 64x32
    const int wm = wid & 3;
    const int wn = wid >> 2;
    const int mbase = wm * 64;
    const int nb    = wn * 32;

    const uint32_t afrag = (uint32_t)(mbase + (lane & 15)) * ROWB + (uint32_t)((lane >> 4) * 16);
    const uint32_t bfrag = (uint32_t)(nb + (lane & 7) + ((lane >> 4) << 3)) * ROWB
                         + (uint32_t)(((lane >> 3) & 1) << 4);

    float4 pf0, pf1;
    auto fptr = [&](int tile) -> const float* {
        int fn = tile * NT + frow;
        if (fn > N - 1) fn = N - 1;              // clamp; stores guarded
        return F + (size_t)fn * 256 + fq * 8;
    };
    auto ldgF = [&](const float* fsrc, int c) {
        const float4* p = (const float4*)(fsrc + c * KC);
        pf0 = p[0]; pf1 = p[1];
    };
    auto stsF = [&](int c) {
        sts128(fb + (uint32_t)(c & 1) * FSTAGE + f_sts,
               pack_f16x2(pf0.y, pf0.x), pack_f16x2(pf0.w, pf0.z),
               pack_f16x2(pf1.y, pf1.x), pack_f16x2(pf1.w, pf1.z));
    };

    // wait for A once
    CP_WAIT0;

    const int stride = gridDim.x;
    #pragma unroll 1
    for (int tile = blockIdx.x; tile < ntiles; tile += stride) {
        const float* fsrc = fptr(tile);
        const int n0 = tile * NT;

        float acc[4][4][4];
        #pragma unroll
        for (int i = 0; i < 4; i++)
            #pragma unroll
            for (int j = 0; j < 4; j++)
                #pragma unroll
                for (int q = 0; q < 4; q++) acc[i][j][q] = 0.0f;

        // F chunk 0 for this tile was LDG'd at the end of the previous tile
        // (or here for the first tile).
        if (tile == blockIdx.x) ldgF(fsrc, 0);
        stsF(0);                   // stage 0: safe vs prior tile (read stage 1 + A only)
        __syncthreads();

        #pragma unroll
        for (int c = 0; c < NCH; c++) {
            if (c + 1 < NCH) ldgF(fsrc, c + 1);
            // ---- compute chunk c from resident A + F stage (c&1) ----
            {
                const uint32_t ast = sb + (uint32_t)c * ACHUNK;
                const uint32_t fst = fb + (uint32_t)(c & 1) * FSTAGE;
                #pragma unroll
                for (int ks = 0; ks < 2; ks++) {
                    const uint32_t ko = ks * 32;
                    uint32_t b0[4], b1[4], a[4][4];
                    ldm4(b0, fst + bfrag + ko);                 // n-tiles 0,1
                    ldm4(b1, fst + bfrag + 16 * ROWB + ko);     // n-tiles 2,3
                    #pragma unroll
                    for (int i = 0; i < 4; i++)
                        ldm4(a[i], ast + afrag + (uint32_t)i * (16 * ROWB) + ko);
                    #pragma unroll
                    for (int i = 0; i < 4; i++) {
                        mma16816(acc[i][0], a[i], b0 + 0);
                        mma16816(acc[i][1], a[i], b0 + 2);
                        mma16816(acc[i][2], a[i], b1 + 0);
                        mma16816(acc[i][3], a[i], b1 + 2);
                    }
                }
            }
            if (c + 1 < NCH) {
                stsF(c + 1);
                __syncthreads();
            }
        }

        // prefetch next tile's F chunk 0 so the epilogue stores hide it
        if (tile + stride < ntiles) ldgF(fptr(tile + stride), 0);

        // ---- epilogue ----
        #pragma unroll
        for (int i = 0; i < 4; i++) {
            const int m = mbase + i * 16 + (lane >> 2);
            #pragma unroll
            for (int j = 0; j < 4; j++) {
                const int n = n0 + nb + j * 8 + (lane & 3) * 2;
                if (n < N) {   // N even, n even -> n+1 also valid
                    float* p0 = C + (size_t)m * N + n;
                    float* p1 = C + (size_t)(m + 8) * N + n;
                    *(float2*)p0 = make_float2(acc[i][j][0] * SCALE, acc[i][j][1] * SCALE);
                    *(float2*)p1 = make_float2(acc[i][j][2] * SCALE, acc[i][j][3] * SCALE);
                }
            }
        }
    }
}

// ---------------- launch ----------------
extern "C" void kernel_launch(void* const* d_in, const int* in_sizes, int n_in,
                              void* d_out, int out_size)
{
    const float* inputs   = (const float*)d_in[0];  // [256, 256]
    const float* features = (const float*)d_in[2];  // [N, 256]
    const int D = 256;
    const int N = in_sizes[2] / D;

    sct_cvtA<<<256, 256>>>(inputs);

    int nsm = 148;
    cudaDeviceGetAttribute(&nsm, cudaDevAttrMultiProcessorCount, 0);

    const int ntiles = (N + NT - 1) / NT;
    int grid = nsm < ntiles ? nsm : ntiles;

    cudaFuncSetAttribute(sct_mma_kernel, cudaFuncAttributeMaxDynamicSharedMemorySize, SMEM_TOTAL);
    sct_mma_kernel<<<grid, 512, SMEM_TOTAL>>>(features, (float*)d_out, N, ntiles);
}